// round 4
// baseline (speedup 1.0000x reference)
#include <cuda_runtime.h>
#include <cuda_fp16.h>
#include <cstdint>
#include <cstddef>

#define B_ 2048
#define T_ 200
#define D_ 4
#define H_ 256
#define G_ 1024
#define CL 8
#define THREADS 256

// smem layout (bytes)
#define SW_OFF   0                         // 8 chunks * 16KB = 128KB
#define RING_OFF (8*16384)                 // 4 slots * 16KB
#define HSTG_OFF (RING_OFF + 4*16384)      // 16KB
#define XROW_OFF (HSTG_OFF + 16384)        // 2KB
#define SWX_OFF  (XROW_OFF + 2048)         // 2KB
#define SMEM_TOTAL (SWX_OFF + 2048)        // 217088

// ---------------- device globals ----------------
__device__ __align__(128) __half g_Wh0[G_ * H_];
__device__ __align__(128) float  g_Wx0[G_ * D_];
__device__ __align__(128) float  g_b0[G_];
__device__ __align__(128) __half g_W1[G_ * 2 * H_];
__device__ __align__(128) float  g_b1[G_];
__device__ __align__(128) __half g_zero[B_ * H_];
__device__ __align__(128) __half g_h1seq[(size_t)T_ * B_ * H_];
__device__ __align__(128) __half g_h2a[B_ * H_];
__device__ __align__(128) __half g_h2b[B_ * H_];
__device__ __align__(128) float  g_h2f[B_ * H_];

// ---------------- init / pack ----------------
__global__ void k_init() {
    int stride = gridDim.x * blockDim.x;
    for (int i = blockIdx.x * blockDim.x + threadIdx.x; i < B_ * H_; i += stride)
        g_zero[i] = __float2half(0.f);
}

__global__ void k_pack0(const float* __restrict__ W_ih0, const float* __restrict__ W_hh0,
                        const float* __restrict__ b_ih0, const float* __restrict__ b_hh0) {
    int stride = gridDim.x * blockDim.x;
    for (int i = blockIdx.x * blockDim.x + threadIdx.x; i < G_ * H_; i += stride) {
        int n = i >> 8, k = i & 255;
        int j = n >> 2, g = n & 3;
        int orow = g * H_ + j;
        g_Wh0[i] = __float2half(W_hh0[orow * H_ + k]);
        if (k < D_) g_Wx0[n * D_ + k] = W_ih0[orow * D_ + k];
        if (k == 0) g_b0[n] = b_ih0[orow] + b_hh0[orow];
    }
}

__global__ void k_pack1(const float* __restrict__ W_ih1, const float* __restrict__ W_hh1,
                        const float* __restrict__ b_ih1, const float* __restrict__ b_hh1) {
    int stride = gridDim.x * blockDim.x;
    for (int i = blockIdx.x * blockDim.x + threadIdx.x; i < G_ * 2 * H_; i += stride) {
        int n = i >> 9, k = i & 511;
        int j = n >> 2, g = n & 3;
        int orow = g * H_ + j;
        float v = (k < H_) ? W_ih1[orow * H_ + k] : W_hh1[orow * H_ + (k - H_)];
        g_W1[i] = __float2half(v);
        if (k == 0) g_b1[n] = b_ih1[orow] + b_hh1[orow];
    }
}

// ---------------- helpers ----------------
__device__ __forceinline__ void cpa16(void* sdst, const void* gsrc) {
    uint32_t sa = (uint32_t)__cvta_generic_to_shared(sdst);
    asm volatile("cp.async.cg.shared.global [%0], [%1], 16;\n" :: "r"(sa), "l"(gsrc));
}
__device__ __forceinline__ void cpcommit() { asm volatile("cp.async.commit_group;\n"); }
__device__ __forceinline__ void cpwait(int n) {
    if (n <= 0)      asm volatile("cp.async.wait_group 0;\n");
    else if (n == 1) asm volatile("cp.async.wait_group 1;\n");
    else             asm volatile("cp.async.wait_group 2;\n");
}
__device__ __forceinline__ void clsync() {
    asm volatile("barrier.cluster.arrive.aligned;\n" ::: "memory");
    asm volatile("barrier.cluster.wait.aligned;\n" ::: "memory");
}
__device__ __forceinline__ float sig_(float x) {
    float e; asm("ex2.approx.ftz.f32 %0, %1;" : "=f"(e) : "f"(x * -1.44269504f));
    float r; asm("rcp.approx.ftz.f32 %0, %1;" : "=f"(r) : "f"(1.0f + e));
    return r;
}
__device__ __forceinline__ float tanh_(float x) { return __fmaf_rn(2.f, sig_(2.f * x), -1.f); }

// A chunk: [128 rows x 64 halves], global row stride H_
__device__ __forceinline__ void load_chunkA(const __half* gp, __half* slot, int tid) {
#pragma unroll
    for (int i = 0; i < 4; i++) {
        int lin = tid + i * THREADS;
        int r = lin >> 3, cch = lin & 7, sc = cch ^ (r & 7);
        cpa16(slot + r * 64 + sc * 8, gp + (size_t)r * H_ + cch * 8);
    }
}
// W chunk: global row stride ws
__device__ __forceinline__ void load_chunkW(const __half* gp, int ws, __half* dst, int tid) {
#pragma unroll
    for (int i = 0; i < 4; i++) {
        int lin = tid + i * THREADS;
        int r = lin >> 3, cch = lin & 7, sc = cch ^ (r & 7);
        cpa16(dst + r * 64 + sc * 8, gp + (size_t)r * ws + cch * 8);
    }
}

// ---------------- one LSTM step ----------------
template<bool XPROJ, int NC, int NCX>
__device__ __forceinline__ void lstm_step(
    const __half* __restrict__ xsrc,   // chunks 0..NCX-1 (pre-offset mbase*H_)
    const __half* __restrict__ hsrc,   // chunks NCX..NC-1
    const float*  __restrict__ xrow_g, // x + (mbase*T + t)*D  (XPROJ only)
    __half* __restrict__ hout,         // + mbase*H_ + rank*32 (null if final)
    float*  __restrict__ hfout,        // fp32 final out, or null
    float* c, const float* biasr,
    char* smem, int tid, int lane, int wm, int wn,
    int a_rowoff, int a_half, int b_rowoff, int b_half)
{
    __half* sW   = (__half*)(smem + SW_OFF);
    __half* ring = (__half*)(smem + RING_OFF);

    float acc[2][8][4];
#pragma unroll
    for (int mi = 0; mi < 2; mi++)
#pragma unroll
        for (int nj = 0; nj < 8; nj++)
#pragma unroll
            for (int e = 0; e < 4; e++) acc[mi][nj][e] = 0.f;

    auto chunk_ptr = [&](int kc) -> const __half* {
        return (kc < NCX) ? (xsrc + kc * 64) : (hsrc + (kc - NCX) * 64);
    };

    if (XPROJ && tid < 128)
        cpa16((float*)(smem + XROW_OFF) + tid * 4, xrow_g + (size_t)tid * (T_ * D_));
    load_chunkA(chunk_ptr(0), ring + 0 * 8192, tid); cpcommit();
    load_chunkA(chunk_ptr(1), ring + 1 * 8192, tid); cpcommit();
    load_chunkA(chunk_ptr(2), ring + 2 * 8192, tid); cpcommit();

#pragma unroll 1
    for (int kc = 0; kc < NC; kc++) {
        int nwait = NC - 1 - kc; if (nwait > 2) nwait = 2;
        cpwait(nwait);
        __syncthreads();
        if (kc + 3 < NC) { load_chunkA(chunk_ptr(kc + 3), ring + ((kc + 3) & 3) * 8192, tid); cpcommit(); }

        __half* sA = ring + (kc & 3) * 8192;
        __half* sB = sW + kc * 8192;

#pragma unroll
        for (int k16 = 0; k16 < 4; k16++) {
            uint32_t afr[2][4];
#pragma unroll
            for (int mi = 0; mi < 2; mi++) {
                int r = wm * 32 + mi * 16 + a_rowoff;
                int cch = (k16 * 2 + a_half) ^ (r & 7);
                uint32_t ad = (uint32_t)__cvta_generic_to_shared(sA + r * 64 + cch * 8);
                asm volatile("ldmatrix.sync.aligned.m8n8.x4.shared.b16 {%0,%1,%2,%3}, [%4];\n"
                             : "=r"(afr[mi][0]), "=r"(afr[mi][1]), "=r"(afr[mi][2]), "=r"(afr[mi][3])
                             : "r"(ad));
            }
            uint32_t bfr[4][4];
#pragma unroll
            for (int np = 0; np < 4; np++) {
                int r = wn * 64 + np * 16 + b_rowoff;
                int cch = (k16 * 2 + b_half) ^ (r & 7);
                uint32_t ad = (uint32_t)__cvta_generic_to_shared(sB + r * 64 + cch * 8);
                asm volatile("ldmatrix.sync.aligned.m8n8.x4.shared.b16 {%0,%1,%2,%3}, [%4];\n"
                             : "=r"(bfr[np][0]), "=r"(bfr[np][1]), "=r"(bfr[np][2]), "=r"(bfr[np][3])
                             : "r"(ad));
            }
#pragma unroll
            for (int mi = 0; mi < 2; mi++)
#pragma unroll
                for (int nj = 0; nj < 8; nj++) {
                    uint32_t b0 = bfr[nj >> 1][(nj & 1) * 2 + 0];
                    uint32_t b1 = bfr[nj >> 1][(nj & 1) * 2 + 1];
                    asm volatile(
                        "mma.sync.aligned.m16n8k16.row.col.f32.f16.f16.f32 "
                        "{%0,%1,%2,%3}, {%4,%5,%6,%7}, {%8,%9}, {%0,%1,%2,%3};\n"
                        : "+f"(acc[mi][nj][0]), "+f"(acc[mi][nj][1]),
                          "+f"(acc[mi][nj][2]), "+f"(acc[mi][nj][3])
                        : "r"(afr[mi][0]), "r"(afr[mi][1]), "r"(afr[mi][2]), "r"(afr[mi][3]),
                          "r"(b0), "r"(b1));
                }
        }
    }

    // ---------- pointwise in registers ----------
    const int q = lane & 3;
    const bool oddq = (q & 1) != 0;
    const bool fin = (hfout != nullptr);
    float*  xrow  = (float*)(smem + XROW_OFF);
    float*  sWx   = (float*)(smem + SWX_OFF);
    __half* hstg  = (__half*)(smem + HSTG_OFF);
    float*  hstgf = (float*)(smem + HSTG_OFF);

#pragma unroll
    for (int mi = 0; mi < 2; mi++) {
        int r0 = wm * 32 + mi * 16 + (lane >> 2);
        float4 xlo = {0,0,0,0}, xhi = {0,0,0,0};
        if (XPROJ) {
            xlo = *(const float4*)&xrow[r0 * 4];
            xhi = *(const float4*)&xrow[(r0 + 8) * 4];
        }
#pragma unroll
        for (int nj = 0; nj < 8; nj++) {
            float a0 = acc[mi][nj][0] + biasr[nj * 2 + 0];
            float a1 = acc[mi][nj][1] + biasr[nj * 2 + 1];
            float a2 = acc[mi][nj][2] + biasr[nj * 2 + 0];
            float a3 = acc[mi][nj][3] + biasr[nj * 2 + 1];
            if (XPROJ) {
                int cl = wn * 64 + nj * 8 + q * 2;   // local col in CTA slice
                float4 w0 = *(const float4*)&sWx[cl * 4];
                float4 w1 = *(const float4*)&sWx[cl * 4 + 4];
                a0 += xlo.x * w0.x + xlo.y * w0.y + xlo.z * w0.z + xlo.w * w0.w;
                a1 += xlo.x * w1.x + xlo.y * w1.y + xlo.z * w1.z + xlo.w * w1.w;
                a2 += xhi.x * w0.x + xhi.y * w0.y + xhi.z * w0.z + xhi.w * w0.w;
                a3 += xhi.x * w1.x + xhi.y * w1.y + xhi.z * w1.z + xhi.w * w1.w;
            }
            float e0 = __shfl_xor_sync(0xffffffffu, a0, 1);
            float e1 = __shfl_xor_sync(0xffffffffu, a1, 1);
            float e2 = __shfl_xor_sync(0xffffffffu, a2, 1);
            float e3 = __shfl_xor_sync(0xffffffffu, a3, 1);
            float gi, gf, gg, go; int row;
            if (!oddq) { gi = a0; gf = a1; gg = e0; go = e1; row = r0; }
            else       { gi = e2; gf = e3; gg = a2; go = a3; row = r0 + 8; }
            int ci = mi * 8 + nj;
            float iv = sig_(gi), fv = sig_(gf), gv = tanh_(gg), ov = sig_(go);
            float cn = fv * c[ci] + iv * gv;
            c[ci] = cn;
            float h = ov * tanh_(cn);
            int jl = wn * 16 + nj * 2 + (q >> 1);    // local hidden 0..31
            if (fin) hstgf[row * 32 + jl] = h;
            else     hstg[row * 32 + jl] = __float2half(h);
        }
    }
    __syncthreads();

    if (!fin) {
#pragma unroll
        for (int p = 0; p < 8; p++) {
            int row = p * 16 + (tid >> 4);
            int cc  = (tid & 15) * 2;
            *(uint32_t*)(hout + (size_t)row * H_ + cc) = *(uint32_t*)&hstg[row * 32 + cc];
        }
    } else {
#pragma unroll
        for (int p = 0; p < 16; p++) {
            int row = p * 8 + (tid >> 5);
            int cc  = tid & 31;
            hfout[(size_t)row * H_ + cc] = hstgf[row * 32 + cc];
        }
    }
    clsync();   // orders h stores (release) before any peer's next-step loads (acquire)
}

// ---------------- persistent kernel ----------------
__global__ void __cluster_dims__(CL, 1, 1) __launch_bounds__(THREADS, 1)
k_lstm(const float* __restrict__ x)
{
    extern __shared__ char smem[];
    const int tid  = threadIdx.x;
    const int lane = tid & 31;
    const int warp = tid >> 5;
    const int wm = warp & 3;
    const int wn = warp >> 2;
    const int rank  = blockIdx.x;          // 0..7 within cluster
    const int mbase = blockIdx.y * 128;    // batch slice
    const int nbase = rank * 128;          // gate-col slice
    const int q = lane & 3;

    const int lg = lane >> 3, lr = lane & 7;
    const int a_rowoff = lr + ((lg & 1) << 3);
    const int a_half   = lg >> 1;
    const int b_rowoff = lr + ((lg >> 1) << 3);
    const int b_half   = lg & 1;

    __half* sW  = (__half*)(smem + SW_OFF);
    float*  sWx = (float*)(smem + SWX_OFF);

    float biasr[16], c[16];

    // ---- phase A: layer 0 (K=256) ----
#pragma unroll
    for (int kc = 0; kc < 4; kc++)
        load_chunkW(g_Wh0 + (size_t)nbase * H_ + kc * 64, H_, sW + kc * 8192, tid);
    if (tid < 128) cpa16(sWx + tid * 4, g_Wx0 + (size_t)(nbase + tid) * D_);
    cpcommit(); cpwait(0); __syncthreads();
#pragma unroll
    for (int nj = 0; nj < 8; nj++) {
        biasr[nj * 2 + 0] = g_b0[nbase + wn * 64 + nj * 8 + q * 2 + 0];
        biasr[nj * 2 + 1] = g_b0[nbase + wn * 64 + nj * 8 + q * 2 + 1];
    }
#pragma unroll
    for (int i = 0; i < 16; i++) c[i] = 0.f;

    const __half* zero_m = g_zero + (size_t)mbase * H_;
#pragma unroll 1
    for (int t = 0; t < T_; t++) {
        const __half* hs = (t == 0) ? zero_m : (g_h1seq + ((size_t)(t - 1) * B_ + mbase) * H_);
        __half* dst = g_h1seq + ((size_t)t * B_ + mbase) * H_ + rank * 32;
        lstm_step<true, 4, 0>(nullptr, hs, x + ((size_t)mbase * T_ + t) * D_,
                              dst, nullptr, c, biasr, smem, tid, lane, wm, wn,
                              a_rowoff, a_half, b_rowoff, b_half);
    }

    // ---- phase B: layer 1 (K=512) ----
#pragma unroll
    for (int kc = 0; kc < 8; kc++)
        load_chunkW(g_W1 + (size_t)nbase * 2 * H_ + kc * 64, 2 * H_, sW + kc * 8192, tid);
    cpcommit(); cpwait(0); __syncthreads();
#pragma unroll
    for (int nj = 0; nj < 8; nj++) {
        biasr[nj * 2 + 0] = g_b1[nbase + wn * 64 + nj * 8 + q * 2 + 0];
        biasr[nj * 2 + 1] = g_b1[nbase + wn * 64 + nj * 8 + q * 2 + 1];
    }
#pragma unroll
    for (int i = 0; i < 16; i++) c[i] = 0.f;

#pragma unroll 1
    for (int t = 0; t < T_; t++) {
        const __half* xs = g_h1seq + ((size_t)t * B_ + mbase) * H_;
        const __half* hs = (t == 0) ? zero_m
                         : ((((t - 1) & 1) ? g_h2b : g_h2a) + (size_t)mbase * H_);
        bool fin = (t == T_ - 1);
        __half* dst = ((t & 1) ? g_h2b : g_h2a) + (size_t)mbase * H_ + rank * 32;
        float* fdst = fin ? (g_h2f + (size_t)mbase * H_ + rank * 32) : (float*)nullptr;
        lstm_step<false, 8, 4>(xs, hs, nullptr, fin ? (/*unused*/(__half*)nullptr) : dst,
                               fdst, c, biasr, smem, tid, lane, wm, wn,
                               a_rowoff, a_half, b_rowoff, b_half);
    }
}

// ---------------- final FC ----------------
__global__ void k_fc(const float* __restrict__ Wfc, const float* __restrict__ bfc,
                     float* __restrict__ out) {
    int b = blockIdx.x;
    int o = threadIdx.y;
    int lane = threadIdx.x;
    const float* hr = g_h2f + (size_t)b * H_;
    const float* wr = Wfc + (size_t)o * H_;
    float s = 0.f;
    for (int j = lane; j < H_; j += 32) s += hr[j] * wr[j];
#pragma unroll
    for (int off = 16; off; off >>= 1) s += __shfl_xor_sync(0xffffffffu, s, off);
    if (lane == 0) out[b * 6 + o] = s + bfc[o];
}

// ---------------- host ----------------
extern "C" void kernel_launch(void* const* d_in, const int* in_sizes, int n_in,
                              void* d_out, int out_size) {
    const float* x     = (const float*)d_in[0];
    const float* W_ih0 = (const float*)d_in[1];
    const float* W_hh0 = (const float*)d_in[2];
    const float* b_ih0 = (const float*)d_in[3];
    const float* b_hh0 = (const float*)d_in[4];
    const float* W_ih1 = (const float*)d_in[5];
    const float* W_hh1 = (const float*)d_in[6];
    const float* b_ih1 = (const float*)d_in[7];
    const float* b_hh1 = (const float*)d_in[8];
    const float* W_fc  = (const float*)d_in[9];
    const float* b_fc  = (const float*)d_in[10];

    static int attr_done = 0;
    if (!attr_done) {
        cudaFuncSetAttribute(k_lstm, cudaFuncAttributeMaxDynamicSharedMemorySize, SMEM_TOTAL);
        attr_done = 1;
    }

    k_init<<<256, 256>>>();
    k_pack0<<<512, 256>>>(W_ih0, W_hh0, b_ih0, b_hh0);
    k_pack1<<<1024, 256>>>(W_ih1, W_hh1, b_ih1, b_hh1);

    k_lstm<<<dim3(CL, 16), THREADS, SMEM_TOTAL>>>(x);

    k_fc<<<B_, dim3(32, 6)>>>(W_fc, b_fc, (float*)d_out);
}

// round 7
// speedup vs baseline: 1.0344x; 1.0344x over previous
#include <cuda_runtime.h>
#include <cuda_fp16.h>
#include <cstdint>
#include <cstddef>

#define B_ 2048
#define T_ 200
#define D_ 4
#define H_ 256
#define G_ 1024
#define CL 8
#define THREADS 256
#define CH 16384
#define TILE 65536

// smem layout (bytes)
#define SW_OFF    0                         // W: up to 8 chunks * 16KB
#define RING_OFF  131072                    // 4 slots * 16KB
#define SBIAS_OFF (RING_OFF + 65536)        // 512B
#define SXW_OFF   (SBIAS_OFF + 512)         // 2KB  (Wx fp32, layer0)
#define SXR_OFF   (SXW_OFF + 2048)          // 2KB  (x rows fp32)
#define SMBAR_OFF (SXR_OFF + 2048)          // 5 mbarriers
#define SMEM_TOTAL (SMBAR_OFF + 64)         // 201280

// ---------------- device globals (all pre-swizzled SMEM images) ----------------
__device__ __align__(128) __half g_W0[G_ * H_];        // 8 ranks * 64KB
__device__ __align__(128) float  g_Wx0[G_ * D_];
__device__ __align__(128) float  g_b0[G_];
__device__ __align__(128) __half g_W1[G_ * 2 * H_];    // 8 ranks * 128KB
__device__ __align__(128) float  g_b1[G_];
__device__ __align__(128) __half g_zero[B_ * H_];
__device__ __align__(128) __half g_h1seq[(size_t)T_ * B_ * H_];  // [t*16+ms] tiles
__device__ __align__(128) __half g_h2a[B_ * H_];
__device__ __align__(128) __half g_h2b[B_ * H_];
__device__ __align__(128) float  g_h2f[B_ * H_];

__global__ void k_init() {
    int s = gridDim.x * blockDim.x;
    for (int i = blockIdx.x * blockDim.x + threadIdx.x; i < B_ * H_; i += s)
        g_zero[i] = __float2half(0.f);
}
// swizzled image address (bytes) for (row r, col k) in a [128 x K] tile, chunk = k>>6
__device__ __forceinline__ size_t swoff(int r, int k) {
    int kc = k >> 6, cc = k & 63, g = cc >> 3, e = cc & 7;
    return (size_t)kc * CH + r * 128 + ((g ^ (r & 7)) << 4) + e * 2;
}
__global__ void k_pack0(const float* __restrict__ Wi, const float* __restrict__ Wh,
                        const float* __restrict__ bi, const float* __restrict__ bh) {
    int s = gridDim.x * blockDim.x;
    for (int i = blockIdx.x * blockDim.x + threadIdx.x; i < G_ * H_; i += s) {
        int n = i >> 8, k = i & 255;
        int j = n >> 2, g = n & 3, orow = g * H_ + j;
        int rank = n >> 7, r = n & 127;
        char* dst = (char*)g_W0 + (size_t)rank * TILE + swoff(r, k);
        *(__half*)dst = __float2half(Wh[orow * H_ + k]);
        if (k < D_) g_Wx0[n * D_ + k] = Wi[orow * D_ + k];
        if (k == 0) g_b0[n] = bi[orow] + bh[orow];
    }
}
__global__ void k_pack1(const float* __restrict__ Wi, const float* __restrict__ Wh,
                        const float* __restrict__ bi, const float* __restrict__ bh) {
    int s = gridDim.x * blockDim.x;
    for (int i = blockIdx.x * blockDim.x + threadIdx.x; i < G_ * 512; i += s) {
        int n = i >> 9, k = i & 511;
        int j = n >> 2, g = n & 3, orow = g * H_ + j;
        int rank = n >> 7, r = n & 127;
        float v = (k < H_) ? Wi[orow * H_ + k] : Wh[orow * H_ + (k - H_)];
        char* dst = (char*)g_W1 + (size_t)rank * 131072 + swoff(r, k);
        *(__half*)dst = __float2half(v);
        if (k == 0) g_b1[n] = bi[orow] + bh[orow];
    }
}

// ---------------- helpers ----------------
__device__ __forceinline__ uint32_t smem_u32(const void* p) {
    uint32_t a;
    asm("{ .reg .u64 t; cvta.to.shared.u64 t, %1; cvt.u32.u64 %0, t; }" : "=r"(a) : "l"(p));
    return a;
}
__device__ __forceinline__ void clsync() {
    asm volatile("barrier.cluster.arrive.aligned;\n" ::: "memory");
    asm volatile("barrier.cluster.wait.aligned;\n" ::: "memory");
}
__device__ __forceinline__ float sig_(float x) {
    float e; asm("ex2.approx.ftz.f32 %0, %1;" : "=f"(e) : "f"(x * -1.44269504f));
    float r; asm("rcp.approx.ftz.f32 %0, %1;" : "=f"(r) : "f"(1.0f + e));
    return r;
}
__device__ __forceinline__ float tanh_(float x) { return __fmaf_rn(2.f, sig_(2.f * x), -1.f); }
__device__ __forceinline__ void mbar_init(uint32_t m, uint32_t c) {
    asm volatile("mbarrier.init.shared.b64 [%0], %1;" :: "r"(m), "r"(c) : "memory");
}
__device__ __forceinline__ void bulk_in(uint32_t sdst, const void* g, uint32_t bytes, uint32_t mb) {
    asm volatile("mbarrier.arrive.expect_tx.shared.b64 _, [%0], %1;" :: "r"(mb), "r"(bytes) : "memory");
    asm volatile("cp.async.bulk.shared::cluster.global.mbarrier::complete_tx::bytes [%0], [%1], %2, [%3];"
                 :: "r"(sdst), "l"(g), "r"(bytes), "r"(mb) : "memory");
}
__device__ __forceinline__ void mbar_wait(uint32_t m, uint32_t par) {
    uint32_t done;
    asm volatile(
        "{\n\t.reg .pred p;\n\t"
        "mbarrier.try_wait.parity.acquire.cta.shared::cta.b64 p, [%1], %2;\n\t"
        "selp.b32 %0, 1, 0, p;\n\t}"
        : "=r"(done) : "r"(m), "r"(par) : "memory");
    if (!done) {
        asm volatile(
            "{\n\t.reg .pred P1;\n\t"
            "WL_%=:\n\t"
            "mbarrier.try_wait.parity.acquire.cta.shared::cta.b64 P1, [%0], %1, 0x989680;\n\t"
            "@P1 bra.uni WD_%=;\n\t"
            "bra.uni WL_%=;\n\t"
            "WD_%=:\n\t}"
            :: "r"(m), "r"(par) : "memory");
    }
}

// ---------------- one LSTM step ----------------
template<bool XPROJ, int NC, int NCX>
__device__ __forceinline__ void run_step(
    const char* __restrict__ src0, const char* __restrict__ src1,
    const float* __restrict__ xrow_g,
    char* __restrict__ hdst_tile, float* __restrict__ fdst,
    float* c, const float* biasr, int* uc,
    char* smem, uint32_t sb32, int tid, int lane, int wm, int wn, int rank,
    int a_rowoff, int a_half, int b_rowoff, int b_half)
{
    float* xrow = (float*)(smem + SXR_OFF);
    if (XPROJ && tid < 128)
        *(float4*)&xrow[tid * 4] = *(const float4*)(xrow_g + (size_t)tid * (T_ * D_));

    if (tid == 0) {
#pragma unroll
        for (int p = 0; p < 3; p++) {
            const char* g = (p < NCX) ? (src0 + p * CH) : (src1 + (p - NCX) * CH);
            bulk_in(sb32 + RING_OFF + p * CH, g, CH, sb32 + SMBAR_OFF + p * 8);
        }
    }

    float acc[2][8][4];
#pragma unroll
    for (int mi = 0; mi < 2; mi++)
#pragma unroll
        for (int nj = 0; nj < 8; nj++)
#pragma unroll
            for (int e = 0; e < 4; e++) acc[mi][nj][e] = 0.f;

#pragma unroll
    for (int kc = 0; kc < NC; kc++) {
        const int s = kc & 3;
        mbar_wait(sb32 + SMBAR_OFF + s * 8, uc[s] & 1);
        uc[s]++;
        const __half* sA = (const __half*)(smem + RING_OFF + s * CH);
        const __half* sB = (const __half*)(smem + SW_OFF + kc * CH);
#pragma unroll
        for (int k16 = 0; k16 < 4; k16++) {
            uint32_t afr[2][4];
#pragma unroll
            for (int mi = 0; mi < 2; mi++) {
                int r = wm * 32 + mi * 16 + a_rowoff;
                int cch = (k16 * 2 + a_half) ^ (r & 7);
                uint32_t ad = (uint32_t)__cvta_generic_to_shared(sA + r * 64 + cch * 8);
                asm volatile("ldmatrix.sync.aligned.m8n8.x4.shared.b16 {%0,%1,%2,%3}, [%4];\n"
                             : "=r"(afr[mi][0]), "=r"(afr[mi][1]), "=r"(afr[mi][2]), "=r"(afr[mi][3])
                             : "r"(ad));
            }
            uint32_t bfr[4][4];
#pragma unroll
            for (int np = 0; np < 4; np++) {
                int r = wn * 64 + np * 16 + b_rowoff;
                int cch = (k16 * 2 + b_half) ^ (r & 7);
                uint32_t ad = (uint32_t)__cvta_generic_to_shared(sB + r * 64 + cch * 8);
                asm volatile("ldmatrix.sync.aligned.m8n8.x4.shared.b16 {%0,%1,%2,%3}, [%4];\n"
                             : "=r"(bfr[np][0]), "=r"(bfr[np][1]), "=r"(bfr[np][2]), "=r"(bfr[np][3])
                             : "r"(ad));
            }
#pragma unroll
            for (int mi = 0; mi < 2; mi++)
#pragma unroll
                for (int nj = 0; nj < 8; nj++) {
                    uint32_t b0 = bfr[nj >> 1][(nj & 1) * 2 + 0];
                    uint32_t b1 = bfr[nj >> 1][(nj & 1) * 2 + 1];
                    asm volatile(
                        "mma.sync.aligned.m16n8k16.row.col.f32.f16.f16.f32 "
                        "{%0,%1,%2,%3}, {%4,%5,%6,%7}, {%8,%9}, {%0,%1,%2,%3};\n"
                        : "+f"(acc[mi][nj][0]), "+f"(acc[mi][nj][1]),
                          "+f"(acc[mi][nj][2]), "+f"(acc[mi][nj][3])
                        : "r"(afr[mi][0]), "r"(afr[mi][1]), "r"(afr[mi][2]), "r"(afr[mi][3]),
                          "r"(b0), "r"(b1));
                }
        }
        __syncthreads();
        if (tid == 0 && kc + 3 < NC) {
            int p = kc + 3;
            const char* g = (p < NCX) ? (src0 + p * CH) : (src1 + (p - NCX) * CH);
            bulk_in(sb32 + RING_OFF + (p & 3) * CH, g, CH, sb32 + SMBAR_OFF + (p & 3) * 8);
        }
    }

    // ---------- pointwise ----------
    const int q = lane & 3;
    const bool oddq = (q & 1) != 0;
    const bool fin = (fdst != nullptr);
    float*  sWx   = (float*)(smem + SXW_OFF);
    __half* hstg  = (__half*)(smem + RING_OFF);
    float*  hstgf = (float*)(smem + RING_OFF);

#pragma unroll
    for (int mi = 0; mi < 2; mi++) {
        int r0 = wm * 32 + mi * 16 + (lane >> 2);
        float4 xlo = {0,0,0,0}, xhi = {0,0,0,0};
        if (XPROJ) {
            xlo = *(const float4*)&xrow[r0 * 4];
            xhi = *(const float4*)&xrow[(r0 + 8) * 4];
        }
#pragma unroll
        for (int nj = 0; nj < 8; nj++) {
            float a0 = acc[mi][nj][0] + biasr[nj * 2 + 0];
            float a1 = acc[mi][nj][1] + biasr[nj * 2 + 1];
            float a2 = acc[mi][nj][2] + biasr[nj * 2 + 0];
            float a3 = acc[mi][nj][3] + biasr[nj * 2 + 1];
            if (XPROJ) {
                int cl = wn * 64 + nj * 8 + q * 2;
                float4 w0 = *(const float4*)&sWx[cl * 4];
                float4 w1 = *(const float4*)&sWx[cl * 4 + 4];
                a0 += xlo.x * w0.x + xlo.y * w0.y + xlo.z * w0.z + xlo.w * w0.w;
                a1 += xlo.x * w1.x + xlo.y * w1.y + xlo.z * w1.z + xlo.w * w1.w;
                a2 += xhi.x * w0.x + xhi.y * w0.y + xhi.z * w0.z + xhi.w * w0.w;
                a3 += xhi.x * w1.x + xhi.y * w1.y + xhi.z * w1.z + xhi.w * w1.w;
            }
            float e0 = __shfl_xor_sync(0xffffffffu, a0, 1);
            float e1 = __shfl_xor_sync(0xffffffffu, a1, 1);
            float e2 = __shfl_xor_sync(0xffffffffu, a2, 1);
            float e3 = __shfl_xor_sync(0xffffffffu, a3, 1);
            float gi, gf, gg, go; int row;
            if (!oddq) { gi = a0; gf = a1; gg = e0; go = e1; row = r0; }
            else       { gi = e2; gf = e3; gg = a2; go = a3; row = r0 + 8; }
            int ci = mi * 8 + nj;
            float iv = sig_(gi), fv = sig_(gf), gv = tanh_(gg), ov = sig_(go);
            float cn = fv * c[ci] + iv * gv;
            c[ci] = cn;
            float h = ov * tanh_(cn);
            int jl = wn * 16 + nj * 2 + (q >> 1);
            if (fin) hstgf[row * 32 + jl] = h;
            else     hstg[row * 32 + jl] = __float2half(h);
        }
    }
    __syncthreads();

    if (!fin) {
        // copy staged h to global as swizzled granules (16B each)
#pragma unroll
        for (int p = 0; p < 2; p++) {
            int idx = tid + p * 256;           // 0..511
            int row = idx >> 2, gg2 = idx & 3;
            uint4 v = *(uint4*)&hstg[row * 32 + gg2 * 8];
            int kcc = rank >> 1;
            int g2 = ((rank & 1) << 2) | gg2;
            *(uint4*)(hdst_tile + kcc * CH + row * 128 + ((g2 ^ (row & 7)) << 4)) = v;
        }
    } else {
        // fdst already offset by rank*32: each rank writes its own 32 columns
#pragma unroll
        for (int p = 0; p < 16; p++) {
            int row = p * 8 + (tid >> 5);
            int cc = tid & 31;
            fdst[(size_t)row * H_ + cc] = hstgf[row * 32 + cc];
        }
    }
    asm volatile("fence.proxy.async;" ::: "memory");
    clsync();
}

// ---------------- persistent kernel ----------------
__global__ void __cluster_dims__(CL, 1, 1) __launch_bounds__(THREADS, 1)
k_lstm(const float* __restrict__ x)
{
    extern __shared__ __align__(1024) char smem[];
    uint32_t sb32 = smem_u32(smem);
    const int tid  = threadIdx.x;
    const int lane = tid & 31;
    const int warp = tid >> 5;
    const int wm = warp & 3;
    const int wn = warp >> 2;
    const int rank = blockIdx.x;
    const int ms   = blockIdx.y;
    const int mbase = ms * 128;
    const int nbase = rank * 128;
    const int q = lane & 3;

    const int lg = lane >> 3, lr = lane & 7;
    const int a_rowoff = lr + ((lg & 1) << 3);
    const int a_half   = lg >> 1;
    const int b_rowoff = lr + ((lg >> 1) << 3);
    const int b_half   = lg & 1;

    if (tid == 0) {
#pragma unroll
        for (int s = 0; s < 5; s++) mbar_init(sb32 + SMBAR_OFF + s * 8, 1);
    }
    __syncthreads();

    float* sbias = (float*)(smem + SBIAS_OFF);
    float* sWx   = (float*)(smem + SXW_OFF);
    float biasr[16], c[16];
    int uc[4] = {0, 0, 0, 0};
    int wph = 0;
    const uint32_t mbW = sb32 + SMBAR_OFF + 32;

    // ---- phase A: layer 0 (K=256, x via pointwise) ----
    if (tid == 0) bulk_in(sb32 + SW_OFF, (char*)g_W0 + (size_t)rank * TILE, TILE, mbW);
    if (tid < 128) {
        sbias[tid] = g_b0[nbase + tid];
        *(float4*)&sWx[tid * 4] = *(const float4*)&g_Wx0[(nbase + tid) * 4];
    }
    mbar_wait(mbW, wph & 1); wph++;
    __syncthreads();
#pragma unroll
    for (int nj = 0; nj < 8; nj++) {
        biasr[nj * 2 + 0] = sbias[wn * 64 + nj * 8 + q * 2 + 0];
        biasr[nj * 2 + 1] = sbias[wn * 64 + nj * 8 + q * 2 + 1];
    }
#pragma unroll
    for (int i = 0; i < 16; i++) c[i] = 0.f;

    const char* zt = (const char*)g_zero + (size_t)ms * TILE;
#pragma unroll 1
    for (int t = 0; t < T_; t++) {
        const char* s1 = (t == 0) ? zt : ((const char*)g_h1seq + ((size_t)(t - 1) * 16 + ms) * TILE);
        char* hd = (char*)g_h1seq + ((size_t)t * 16 + ms) * TILE;
        run_step<true, 4, 0>(s1, s1, x + ((size_t)mbase * T_ + t) * D_,
                             hd, nullptr, c, biasr, uc,
                             smem, sb32, tid, lane, wm, wn, rank,
                             a_rowoff, a_half, b_rowoff, b_half);
    }

    // ---- phase B: layer 1 (K=512) ----
    if (tid == 0) bulk_in(sb32 + SW_OFF, (char*)g_W1 + (size_t)rank * 131072, 131072, mbW);
    if (tid < 128) sbias[tid] = g_b1[nbase + tid];
    mbar_wait(mbW, wph & 1); wph++;
    __syncthreads();
#pragma unroll
    for (int nj = 0; nj < 8; nj++) {
        biasr[nj * 2 + 0] = sbias[wn * 64 + nj * 8 + q * 2 + 0];
        biasr[nj * 2 + 1] = sbias[wn * 64 + nj * 8 + q * 2 + 1];
    }
#pragma unroll
    for (int i = 0; i < 16; i++) c[i] = 0.f;

#pragma unroll 1
    for (int t = 0; t < T_; t++) {
        const char* s0 = (const char*)g_h1seq + ((size_t)t * 16 + ms) * TILE;
        const char* s1 = (t == 0) ? zt
                       : (const char*)(((t - 1) & 1) ? g_h2b : g_h2a) + (size_t)ms * TILE;
        bool fin = (t == T_ - 1);
        char* hd = (char*)((t & 1) ? g_h2b : g_h2a) + (size_t)ms * TILE;
        float* fd = fin ? (g_h2f + (size_t)mbase * H_ + rank * 32) : (float*)nullptr;
        run_step<false, 8, 4>(s0, s1, nullptr, hd, fd, c, biasr, uc,
                              smem, sb32, tid, lane, wm, wn, rank,
                              a_rowoff, a_half, b_rowoff, b_half);
    }
}

// ---------------- final FC ----------------
__global__ void k_fc(const float* __restrict__ Wfc, const float* __restrict__ bfc,
                     float* __restrict__ out) {
    int b = blockIdx.x;
    int o = threadIdx.y;
    int lane = threadIdx.x;
    const float* hr = g_h2f + (size_t)b * H_;
    const float* wr = Wfc + (size_t)o * H_;
    float s = 0.f;
    for (int j = lane; j < H_; j += 32) s += hr[j] * wr[j];
#pragma unroll
    for (int off = 16; off; off >>= 1) s += __shfl_xor_sync(0xffffffffu, s, off);
    if (lane == 0) out[b * 6 + o] = s + bfc[o];
}

// ---------------- host ----------------
extern "C" void kernel_launch(void* const* d_in, const int* in_sizes, int n_in,
                              void* d_out, int out_size) {
    const float* x     = (const float*)d_in[0];
    const float* W_ih0 = (const float*)d_in[1];
    const float* W_hh0 = (const float*)d_in[2];
    const float* b_ih0 = (const float*)d_in[3];
    const float* b_hh0 = (const float*)d_in[4];
    const float* W_ih1 = (const float*)d_in[5];
    const float* W_hh1 = (const float*)d_in[6];
    const float* b_ih1 = (const float*)d_in[7];
    const float* b_hh1 = (const float*)d_in[8];
    const float* W_fc  = (const float*)d_in[9];
    const float* b_fc  = (const float*)d_in[10];

    cudaFuncSetAttribute(k_lstm, cudaFuncAttributeMaxDynamicSharedMemorySize, SMEM_TOTAL);

    k_init<<<256, 256>>>();
    k_pack0<<<512, 256>>>(W_ih0, W_hh0, b_ih0, b_hh0);
    k_pack1<<<1024, 256>>>(W_ih1, W_hh1, b_ih1, b_hh1);

    k_lstm<<<dim3(CL, 16), THREADS, SMEM_TOTAL>>>(x);

    k_fc<<<B_, dim3(32, 6)>>>(W_fc, b_fc, (float*)d_out);
}

// round 8
// speedup vs baseline: 1.1223x; 1.0850x over previous
#include <cuda_runtime.h>
#include <cuda_fp16.h>
#include <cstdint>
#include <cstddef>

#define B_ 2048
#define T_ 200
#define D_ 4
#define H_ 256
#define G_ 1024
#define CL 8
#define THREADS 512
#define CH 16384
#define TILE 65536

// smem layout (bytes)
#define SW_OFF    0                       // W: up to 8 chunks * 16KB = 128KB
#define SXW_OFF   65536                   // phase A only (upper half of W region): Wx fp32
#define SXR_OFF   (SXW_OFF + 2048)        // phase A only: x rows fp32
#define RING_OFF  131072                  // 6 slots * 16KB = 96KB
#define HSTG_OFF  (RING_OFF + 4*CH)       // h staging = ring slot 4 (16KB)
#define SMBAR_OFF (RING_OFF + 6*CH)       // 7 mbarriers
#define SMEM_TOTAL (SMBAR_OFF + 64)       // 229440 (< 232448 limit)

// ---------------- device globals (pre-swizzled SMEM images) ----------------
__device__ __align__(128) __half g_W0[G_ * H_];        // 8 ranks * 64KB
__device__ __align__(128) float  g_Wx0[G_ * D_];
__device__ __align__(128) float  g_b0[G_];
__device__ __align__(128) __half g_W1[G_ * 2 * H_];    // 8 ranks * 128KB
__device__ __align__(128) float  g_b1[G_];
__device__ __align__(128) __half g_zero[B_ * H_];
__device__ __align__(128) __half g_h1seq[(size_t)T_ * B_ * H_];  // [t*16+ms] tiles
__device__ __align__(128) __half g_h2a[B_ * H_];
__device__ __align__(128) __half g_h2b[B_ * H_];
__device__ __align__(128) float  g_h2f[B_ * H_];

__global__ void k_init() {
    int s = gridDim.x * blockDim.x;
    for (int i = blockIdx.x * blockDim.x + threadIdx.x; i < B_ * H_; i += s)
        g_zero[i] = __float2half(0.f);
}
// swizzled image address (bytes) for (row r, col k) in a [128 x K] tile, chunk = k>>6
__device__ __forceinline__ size_t swoff(int r, int k) {
    int kc = k >> 6, cc = k & 63, g = cc >> 3, e = cc & 7;
    return (size_t)kc * CH + r * 128 + ((g ^ (r & 7)) << 4) + e * 2;
}
__global__ void k_pack0(const float* __restrict__ Wi, const float* __restrict__ Wh,
                        const float* __restrict__ bi, const float* __restrict__ bh) {
    int s = gridDim.x * blockDim.x;
    for (int i = blockIdx.x * blockDim.x + threadIdx.x; i < G_ * H_; i += s) {
        int n = i >> 8, k = i & 255;
        int j = n >> 2, g = n & 3, orow = g * H_ + j;
        int rank = n >> 7, r = n & 127;
        char* dst = (char*)g_W0 + (size_t)rank * TILE + swoff(r, k);
        *(__half*)dst = __float2half(Wh[orow * H_ + k]);
        if (k < D_) g_Wx0[n * D_ + k] = Wi[orow * D_ + k];
        if (k == 0) g_b0[n] = bi[orow] + bh[orow];
    }
}
__global__ void k_pack1(const float* __restrict__ Wi, const float* __restrict__ Wh,
                        const float* __restrict__ bi, const float* __restrict__ bh) {
    int s = gridDim.x * blockDim.x;
    for (int i = blockIdx.x * blockDim.x + threadIdx.x; i < G_ * 512; i += s) {
        int n = i >> 9, k = i & 511;
        int j = n >> 2, g = n & 3, orow = g * H_ + j;
        int rank = n >> 7, r = n & 127;
        float v = (k < H_) ? Wi[orow * H_ + k] : Wh[orow * H_ + (k - H_)];
        char* dst = (char*)g_W1 + (size_t)rank * 131072 + swoff(r, k);
        *(__half*)dst = __float2half(v);
        if (k == 0) g_b1[n] = bi[orow] + bh[orow];
    }
}

// ---------------- helpers ----------------
__device__ __forceinline__ uint32_t smem_u32(const void* p) {
    uint32_t a;
    asm("{ .reg .u64 t; cvta.to.shared.u64 t, %1; cvt.u32.u64 %0, t; }" : "=r"(a) : "l"(p));
    return a;
}
__device__ __forceinline__ void clsync() {
    asm volatile("barrier.cluster.arrive.aligned;\n" ::: "memory");
    asm volatile("barrier.cluster.wait.aligned;\n" ::: "memory");
}
__device__ __forceinline__ float sig_(float x) {
    float e; asm("ex2.approx.ftz.f32 %0, %1;" : "=f"(e) : "f"(x * -1.44269504f));
    float r; asm("rcp.approx.ftz.f32 %0, %1;" : "=f"(r) : "f"(1.0f + e));
    return r;
}
__device__ __forceinline__ float tanh_(float x) { return __fmaf_rn(2.f, sig_(2.f * x), -1.f); }
__device__ __forceinline__ void mbar_init(uint32_t m, uint32_t c) {
    asm volatile("mbarrier.init.shared.b64 [%0], %1;" :: "r"(m), "r"(c) : "memory");
}
__device__ __forceinline__ void bulk_in(uint32_t sdst, const void* g, uint32_t bytes, uint32_t mb) {
    asm volatile("mbarrier.arrive.expect_tx.shared.b64 _, [%0], %1;" :: "r"(mb), "r"(bytes) : "memory");
    asm volatile("cp.async.bulk.shared::cluster.global.mbarrier::complete_tx::bytes [%0], [%1], %2, [%3];"
                 :: "r"(sdst), "l"(g), "r"(bytes), "r"(mb) : "memory");
}
__device__ __forceinline__ void mbar_wait(uint32_t m, uint32_t par) {
    uint32_t done;
    asm volatile(
        "{\n\t.reg .pred p;\n\t"
        "mbarrier.try_wait.parity.acquire.cta.shared::cta.b64 p, [%1], %2;\n\t"
        "selp.b32 %0, 1, 0, p;\n\t}"
        : "=r"(done) : "r"(m), "r"(par) : "memory");
    if (!done) {
        asm volatile(
            "{\n\t.reg .pred P1;\n\t"
            "WL_%=:\n\t"
            "mbarrier.try_wait.parity.acquire.cta.shared::cta.b64 P1, [%0], %1, 0x989680;\n\t"
            "@P1 bra.uni WD_%=;\n\t"
            "bra.uni WL_%=;\n\t"
            "WD_%=:\n\t}"
            :: "r"(m), "r"(par) : "memory");
    }
}

// ---------------- one LSTM step ----------------
// Phase A (PHB=false): 4 h chunks, x via pointwise. Phase B (PHB=true): 8 chunks,
// x chunks 0-3 pre-fetched into ring slots 0-3 by the PREVIOUS step; h chunks 4-7.
template<bool PHB>
__device__ __forceinline__ void run_step(
    const char* __restrict__ hsrc,        // h tile (4 chunks)
    const char* __restrict__ nx,          // PHB: next-step x tile to prefetch (or null)
    const float* __restrict__ xrow_g,     // phase A: x + (mbase*T + t)*D
    char* __restrict__ hdst_tile, float* __restrict__ fdst,
    float* c, const float* biasr, int* uc,
    char* smem, uint32_t sb32, int tid, int lane, int wm, int wn, int rank,
    int a_rowoff, int a_half, int b_rowoff, int b_half)
{
    if (!PHB && tid < 128)
        *(float4*)((float*)(smem + SXR_OFF) + tid * 4) =
            *(const float4*)(xrow_g + (size_t)tid * (T_ * D_));

    if (tid == 0) {
        if (PHB) {
            bulk_in(sb32 + RING_OFF + 4 * CH, hsrc + 0 * CH, CH, sb32 + SMBAR_OFF + 4 * 8);
            bulk_in(sb32 + RING_OFF + 5 * CH, hsrc + 1 * CH, CH, sb32 + SMBAR_OFF + 5 * 8);
        } else {
#pragma unroll
            for (int p = 0; p < 4; p++)
                bulk_in(sb32 + RING_OFF + p * CH, hsrc + p * CH, CH, sb32 + SMBAR_OFF + p * 8);
        }
    }

    float acc[2][4][4];
#pragma unroll
    for (int mi = 0; mi < 2; mi++)
#pragma unroll
        for (int nj = 0; nj < 4; nj++)
#pragma unroll
            for (int e = 0; e < 4; e++) acc[mi][nj][e] = 0.f;

    const int NC = PHB ? 8 : 4;
#pragma unroll
    for (int kc = 0; kc < NC; kc++) {
        const int s = (kc < 6) ? kc : kc - 6;
        mbar_wait(sb32 + SMBAR_OFF + s * 8, uc[s] & 1);
        uc[s]++;
        const __half* sA = (const __half*)(smem + RING_OFF + s * CH);
        const __half* sB = (const __half*)(smem + SW_OFF + kc * CH);
#pragma unroll
        for (int k16 = 0; k16 < 4; k16++) {
            uint32_t afr[2][4];
#pragma unroll
            for (int mi = 0; mi < 2; mi++) {
                int r = wm * 32 + mi * 16 + a_rowoff;
                int cch = (k16 * 2 + a_half) ^ (r & 7);
                uint32_t ad = (uint32_t)__cvta_generic_to_shared(sA + r * 64 + cch * 8);
                asm volatile("ldmatrix.sync.aligned.m8n8.x4.shared.b16 {%0,%1,%2,%3}, [%4];\n"
                             : "=r"(afr[mi][0]), "=r"(afr[mi][1]), "=r"(afr[mi][2]), "=r"(afr[mi][3])
                             : "r"(ad));
            }
            uint32_t bfr[2][4];
#pragma unroll
            for (int np = 0; np < 2; np++) {
                int r = wn * 32 + np * 16 + b_rowoff;
                int cch = (k16 * 2 + b_half) ^ (r & 7);
                uint32_t ad = (uint32_t)__cvta_generic_to_shared(sB + r * 64 + cch * 8);
                asm volatile("ldmatrix.sync.aligned.m8n8.x4.shared.b16 {%0,%1,%2,%3}, [%4];\n"
                             : "=r"(bfr[np][0]), "=r"(bfr[np][1]), "=r"(bfr[np][2]), "=r"(bfr[np][3])
                             : "r"(ad));
            }
#pragma unroll
            for (int mi = 0; mi < 2; mi++)
#pragma unroll
                for (int nj = 0; nj < 4; nj++) {
                    uint32_t b0 = bfr[nj >> 1][(nj & 1) * 2 + 0];
                    uint32_t b1 = bfr[nj >> 1][(nj & 1) * 2 + 1];
                    asm volatile(
                        "mma.sync.aligned.m16n8k16.row.col.f32.f16.f16.f32 "
                        "{%0,%1,%2,%3}, {%4,%5,%6,%7}, {%8,%9}, {%0,%1,%2,%3};\n"
                        : "+f"(acc[mi][nj][0]), "+f"(acc[mi][nj][1]),
                          "+f"(acc[mi][nj][2]), "+f"(acc[mi][nj][3])
                        : "r"(afr[mi][0]), "r"(afr[mi][1]), "r"(afr[mi][2]), "r"(afr[mi][3]),
                          "r"(b0), "r"(b1));
                }
        }
        // after x0/x1 fully consumed, their slots take h2/h3
        if (PHB && kc <= 1) {
            __syncthreads();
            if (tid == 0)
                bulk_in(sb32 + RING_OFF + kc * CH, hsrc + (2 + kc) * CH, CH,
                        sb32 + SMBAR_OFF + kc * 8);
        }
    }
    __syncthreads();   // all chunk reads complete; safe to prefetch + write hstg (slot 4)
    if (PHB && tid == 0 && nx) {
#pragma unroll
        for (int p = 0; p < 4; p++)
            bulk_in(sb32 + RING_OFF + p * CH, nx + p * CH, CH, sb32 + SMBAR_OFF + p * 8);
    }

    // ---------- pointwise ----------
    const int q = lane & 3;
    const bool oddq = (q & 1) != 0;
    const bool fin = (fdst != nullptr);
    float*  xrow  = (float*)(smem + SXR_OFF);
    float*  sWx   = (float*)(smem + SXW_OFF);
    __half* hstg  = (__half*)(smem + HSTG_OFF);
    float*  hstgf = (float*)(smem + HSTG_OFF);

#pragma unroll
    for (int mi = 0; mi < 2; mi++) {
        int r0 = wm * 32 + mi * 16 + (lane >> 2);
        float4 xlo = {0,0,0,0}, xhi = {0,0,0,0};
        if (!PHB) {
            xlo = *(const float4*)&xrow[r0 * 4];
            xhi = *(const float4*)&xrow[(r0 + 8) * 4];
        }
#pragma unroll
        for (int nj = 0; nj < 4; nj++) {
            float a0 = acc[mi][nj][0] + biasr[nj * 2 + 0];
            float a1 = acc[mi][nj][1] + biasr[nj * 2 + 1];
            float a2 = acc[mi][nj][2] + biasr[nj * 2 + 0];
            float a3 = acc[mi][nj][3] + biasr[nj * 2 + 1];
            if (!PHB) {
                int cl = wn * 32 + nj * 8 + q * 2;
                float4 w0 = *(const float4*)&sWx[cl * 4];
                float4 w1 = *(const float4*)&sWx[cl * 4 + 4];
                a0 += xlo.x * w0.x + xlo.y * w0.y + xlo.z * w0.z + xlo.w * w0.w;
                a1 += xlo.x * w1.x + xlo.y * w1.y + xlo.z * w1.z + xlo.w * w1.w;
                a2 += xhi.x * w0.x + xhi.y * w0.y + xhi.z * w0.z + xhi.w * w0.w;
                a3 += xhi.x * w1.x + xhi.y * w1.y + xhi.z * w1.z + xhi.w * w1.w;
            }
            float e0 = __shfl_xor_sync(0xffffffffu, a0, 1);
            float e1 = __shfl_xor_sync(0xffffffffu, a1, 1);
            float e2 = __shfl_xor_sync(0xffffffffu, a2, 1);
            float e3 = __shfl_xor_sync(0xffffffffu, a3, 1);
            float gi, gf, gg, go; int row;
            if (!oddq) { gi = a0; gf = a1; gg = e0; go = e1; row = r0; }
            else       { gi = e2; gf = e3; gg = a2; go = a3; row = r0 + 8; }
            int ci = mi * 4 + nj;
            float iv = sig_(gi), fv = sig_(gf), gv = tanh_(gg), ov = sig_(go);
            float cn = fv * c[ci] + iv * gv;
            c[ci] = cn;
            float h = ov * tanh_(cn);
            int jl = wn * 8 + nj * 2 + (q >> 1);     // local hidden 0..31
            if (fin) hstgf[row * 32 + jl] = h;
            else     hstg[row * 32 + jl] = __float2half(h);
        }
    }
    __syncthreads();

    if (!fin) {
        // one 16B swizzled granule per thread (512 granules = 128 rows x 4)
        int row = tid >> 2, gg2 = tid & 3;
        uint4 v = *(uint4*)&hstg[row * 32 + gg2 * 8];
        int kcc = rank >> 1;
        int g2 = ((rank & 1) << 2) | gg2;
        *(uint4*)(hdst_tile + kcc * CH + row * 128 + ((g2 ^ (row & 7)) << 4)) = v;
    } else {
        // fdst pre-offset by rank*32: each rank owns its 32 columns
#pragma unroll
        for (int p = 0; p < 8; p++) {
            int row = p * 16 + (tid >> 5);
            int cc = tid & 31;
            fdst[(size_t)row * H_ + cc] = hstgf[row * 32 + cc];
        }
    }
    asm volatile("fence.proxy.async;" ::: "memory");
    clsync();
}

// ---------------- persistent kernel ----------------
__global__ void __cluster_dims__(CL, 1, 1) __launch_bounds__(THREADS, 1)
k_lstm(const float* __restrict__ x)
{
    extern __shared__ __align__(1024) char smem[];
    uint32_t sb32 = smem_u32(smem);
    const int tid  = threadIdx.x;
    const int lane = tid & 31;
    const int warp = tid >> 5;
    const int wm = warp & 3;     // 4 M-groups of 32 rows
    const int wn = warp >> 2;    // 4 N-groups of 32 cols
    const int rank = blockIdx.x;
    const int ms   = blockIdx.y;
    const int mbase = ms * 128;
    const int nbase = rank * 128;
    const int q = lane & 3;

    const int lg = lane >> 3, lr = lane & 7;
    const int a_rowoff = lr + ((lg & 1) << 3);
    const int a_half   = lg >> 1;
    const int b_rowoff = lr + ((lg >> 1) << 3);
    const int b_half   = lg & 1;

    if (tid == 0) {
#pragma unroll
        for (int s = 0; s < 7; s++) mbar_init(sb32 + SMBAR_OFF + s * 8, 1);
    }
    __syncthreads();

    float* sWx = (float*)(smem + SXW_OFF);
    float biasr[8], c[8];
    int uc[6] = {0, 0, 0, 0, 0, 0};
    const uint32_t mbW = sb32 + SMBAR_OFF + 48;

    // ---- phase A: layer 0 (K=256, x via pointwise) ----
    if (tid == 0) bulk_in(sb32 + SW_OFF, (char*)g_W0 + (size_t)rank * TILE, TILE, mbW);
    if (tid < 128)
        *(float4*)&sWx[tid * 4] = *(const float4*)&g_Wx0[(nbase + tid) * 4];
#pragma unroll
    for (int nj = 0; nj < 4; nj++) {
        biasr[nj * 2 + 0] = g_b0[nbase + wn * 32 + nj * 8 + q * 2 + 0];
        biasr[nj * 2 + 1] = g_b0[nbase + wn * 32 + nj * 8 + q * 2 + 1];
    }
#pragma unroll
    for (int i = 0; i < 8; i++) c[i] = 0.f;
    mbar_wait(mbW, 0);
    __syncthreads();

    const char* zt = (const char*)g_zero + (size_t)ms * TILE;
#pragma unroll 1
    for (int t = 0; t < T_; t++) {
        const char* s1 = (t == 0) ? zt : ((const char*)g_h1seq + ((size_t)(t - 1) * 16 + ms) * TILE);
        char* hd = (char*)g_h1seq + ((size_t)t * 16 + ms) * TILE;
        run_step<false>(s1, nullptr, x + ((size_t)mbase * T_ + t) * D_,
                        hd, nullptr, c, biasr, uc,
                        smem, sb32, tid, lane, wm, wn, rank,
                        a_rowoff, a_half, b_rowoff, b_half);
    }

    // ---- phase B: layer 1 (K=512; x chunks prefetched, h chunks per step) ----
    if (tid == 0) {
        bulk_in(sb32 + SW_OFF, (char*)g_W1 + (size_t)rank * 131072, 131072, mbW);
#pragma unroll
        for (int p = 0; p < 4; p++)
            bulk_in(sb32 + RING_OFF + p * CH,
                    (const char*)g_h1seq + (size_t)ms * TILE + p * CH, CH,
                    sb32 + SMBAR_OFF + p * 8);
    }
#pragma unroll
    for (int nj = 0; nj < 4; nj++) {
        biasr[nj * 2 + 0] = g_b1[nbase + wn * 32 + nj * 8 + q * 2 + 0];
        biasr[nj * 2 + 1] = g_b1[nbase + wn * 32 + nj * 8 + q * 2 + 1];
    }
#pragma unroll
    for (int i = 0; i < 8; i++) c[i] = 0.f;
    mbar_wait(mbW, 1);

#pragma unroll 1
    for (int t = 0; t < T_; t++) {
        const char* s1 = (t == 0) ? zt
                       : (const char*)(((t - 1) & 1) ? g_h2b : g_h2a) + (size_t)ms * TILE;
        const char* nx = (t + 1 < T_)
                       ? ((const char*)g_h1seq + ((size_t)(t + 1) * 16 + ms) * TILE)
                       : (const char*)nullptr;
        bool fin = (t == T_ - 1);
        char* hd = (char*)((t & 1) ? g_h2b : g_h2a) + (size_t)ms * TILE;
        float* fd = fin ? (g_h2f + (size_t)mbase * H_ + rank * 32) : (float*)nullptr;
        run_step<true>(s1, nx, nullptr, hd, fd, c, biasr, uc,
                       smem, sb32, tid, lane, wm, wn, rank,
                       a_rowoff, a_half, b_rowoff, b_half);
    }
}

// ---------------- final FC ----------------
__global__ void k_fc(const float* __restrict__ Wfc, const float* __restrict__ bfc,
                     float* __restrict__ out) {
    int b = blockIdx.x;
    int o = threadIdx.y;
    int lane = threadIdx.x;
    const float* hr = g_h2f + (size_t)b * H_;
    const float* wr = Wfc + (size_t)o * H_;
    float s = 0.f;
    for (int j = lane; j < H_; j += 32) s += hr[j] * wr[j];
#pragma unroll
    for (int off = 16; off; off >>= 1) s += __shfl_xor_sync(0xffffffffu, s, off);
    if (lane == 0) out[b * 6 + o] = s + bfc[o];
}

// ---------------- host ----------------
extern "C" void kernel_launch(void* const* d_in, const int* in_sizes, int n_in,
                              void* d_out, int out_size) {
    const float* x     = (const float*)d_in[0];
    const float* W_ih0 = (const float*)d_in[1];
    const float* W_hh0 = (const float*)d_in[2];
    const float* b_ih0 = (const float*)d_in[3];
    const float* b_hh0 = (const float*)d_in[4];
    const float* W_ih1 = (const float*)d_in[5];
    const float* W_hh1 = (const float*)d_in[6];
    const float* b_ih1 = (const float*)d_in[7];
    const float* b_hh1 = (const float*)d_in[8];
    const float* W_fc  = (const float*)d_in[9];
    const float* b_fc  = (const float*)d_in[10];

    cudaFuncSetAttribute(k_lstm, cudaFuncAttributeMaxDynamicSharedMemorySize, SMEM_TOTAL);

    k_init<<<256, 256>>>();
    k_pack0<<<512, 256>>>(W_ih0, W_hh0, b_ih0, b_hh0);
    k_pack1<<<1024, 256>>>(W_ih1, W_hh1, b_ih1, b_hh1);

    k_lstm<<<dim3(CL, 16), THREADS, SMEM_TOTAL>>>(x);

    k_fc<<<B_, dim3(32, 6)>>>(W_fc, b_fc, (float*)d_out);
}